// round 12
// baseline (speedup 1.0000x reference)
#include <cuda_runtime.h>
#include <math.h>
#include <stdint.h>

#define B_ 2
#define T_ 2048
#define C_ 1024
#define H_ 16
#define D_ 64
#define M_ 4096
#define K2L 0.18033688f   // 0.125 * log2(e)

// Scratch (allocation-free)
__device__ float g_xr[M_*C_];
__device__ float g_Wr[4][C_*C_];
__device__ float g_Q [M_*C_];
__device__ float g_K [M_*C_];
__device__ float g_V [M_*C_];
__device__ float g_Vt[B_*H_*D_*T_];
__device__ float g_AO[M_*C_];

// ---------------------------------------------------------------------------
__device__ __forceinline__ float tf32r(float x) {
    uint32_t u; asm("cvt.rna.tf32.f32 %0, %1;" : "=r"(u) : "f"(x));
    return __uint_as_float(u);
}
__host__ __device__ __forceinline__ int perm8(int k) { return ((k & 3) << 1) | (k >> 2); }
__device__ __forceinline__ uint32_t s2u(const void* p) {
    return (uint32_t)__cvta_generic_to_shared(p);
}
__device__ __forceinline__ void cpa16(uint32_t d, const void* s) {
    asm volatile("cp.async.cg.shared.global [%0], [%1], 16;\n" :: "r"(d), "l"(s));
}
#define CPCOMMIT() asm volatile("cp.async.commit_group;\n")
#define CPWAIT0()  asm volatile("cp.async.wait_group 0;\n")
__device__ __forceinline__ float ex2f(float x) {
    float y; asm("ex2.approx.ftz.f32 %0, %1;" : "=f"(y) : "f"(x)); return y;
}
__device__ __forceinline__ void mma_tf32(float* c, const uint32_t* a, const uint32_t* b) {
    asm volatile(
        "mma.sync.aligned.m16n8k8.row.col.f32.tf32.tf32.f32 "
        "{%0,%1,%2,%3}, {%4,%5,%6,%7}, {%8,%9}, {%0,%1,%2,%3};\n"
        : "+f"(c[0]), "+f"(c[1]), "+f"(c[2]), "+f"(c[3])
        : "r"(a[0]), "r"(a[1]), "r"(a[2]), "r"(a[3]), "r"(b[0]), "r"(b[1]));
}

// ---------------------------------------------------------------------------
// Prepass: round to tf32 + permute k within 8-groups (two float4 stores).
// ---------------------------------------------------------------------------
__device__ __forceinline__ void prep8(const float* __restrict__ s, float* __restrict__ d) {
    float4 a = *(const float4*)(s);
    float4 b = *(const float4*)(s + 4);
    *(float4*)(d)     = make_float4(tf32r(a.x), tf32r(b.x), tf32r(a.y), tf32r(b.y));
    *(float4*)(d + 4) = make_float4(tf32r(a.z), tf32r(b.z), tf32r(a.w), tf32r(b.w));
}
__global__ void prep_x(const float* __restrict__ src, float* __restrict__ dst) {
    int i = (blockIdx.x * blockDim.x + threadIdx.x) * 8;
    prep8(src + i, dst + i);
}
__global__ void prep_w(const float* w0, const float* w1, const float* w2,
                       const float* w3, float* __restrict__ dst) {
    const float* src = (blockIdx.y == 0) ? w0 : (blockIdx.y == 1) ? w1
                     : (blockIdx.y == 2) ? w2 : w3;
    float* d = dst + (long)blockIdx.y * C_ * C_;
    int i = (blockIdx.x * blockDim.x + threadIdx.x) * 8;
    prep8(src + i, d + i);
}

// ---------------------------------------------------------------------------
// GEMM-NT (tf32 mma.sync): validated 120 TF/s pipeline (R9).
// MODE 0: plain fp32 out. MODE 3: fused QKV epilogue.
// ---------------------------------------------------------------------------
#define GST 36
#define GEMM_SMEM (4 * 128 * GST * 4)

template<int MODE>
__global__ void __launch_bounds__(256)
gemm_tc(const float* __restrict__ A, const float* __restrict__ Bm,
        float* __restrict__ Cm, float* __restrict__ Cq,
        float* __restrict__ Ck, float* __restrict__ Cv)
{
    extern __shared__ float sh[];
    float* As = sh;
    float* Bs = sh + 2 * 128 * GST;

    const int tid = threadIdx.x, lane = tid & 31, warp = tid >> 5;
    const int gid = lane >> 2, tig = lane & 3;
    const int wm = warp & 3, wn = warp >> 2;
    const int bm = blockIdx.y * 128, bn = blockIdx.x * 128;
    const int frow = tid >> 3, fcol = (tid & 7) << 2;
    const int ko2 = 2 * tig;

    float acc[2][8][4];
    #pragma unroll
    for (int mt = 0; mt < 2; mt++)
        #pragma unroll
        for (int nt = 0; nt < 8; nt++)
            #pragma unroll
            for (int e = 0; e < 4; e++) acc[mt][nt][e] = 0.f;

    auto loadst = [&](int s, int kt) {
        #pragma unroll
        for (int p = 0; p < 4; p++) {
            int row = frow + p * 32;
            cpa16(s2u(&As[(s * 128 + row) * GST + fcol]),
                  &A[(long)(bm + row) * C_ + kt + fcol]);
            cpa16(s2u(&Bs[(s * 128 + row) * GST + fcol]),
                  &Bm[(long)(bn + row) * C_ + kt + fcol]);
        }
    };

    loadst(0, 0); CPCOMMIT();

    #pragma unroll 2
    for (int t = 0; t < 32; t++) {
        CPWAIT0(); __syncthreads();
        if (t + 1 < 32) { loadst((t + 1) & 1, (t + 1) * 32); CPCOMMIT(); }
        const float* as = As + (t & 1) * 128 * GST;
        const float* bs = Bs + (t & 1) * 128 * GST;
        #pragma unroll
        for (int ks = 0; ks < 4; ks++) {
            int ko = ks * 8 + ko2;
            uint32_t a[2][4];
            #pragma unroll
            for (int mt = 0; mt < 2; mt++) {
                int r = wm * 32 + mt * 16 + gid;
                uint2 lo = *(const uint2*)&as[r * GST + ko];
                uint2 hi = *(const uint2*)&as[(r + 8) * GST + ko];
                a[mt][0] = lo.x; a[mt][1] = hi.x; a[mt][2] = lo.y; a[mt][3] = hi.y;
            }
            #pragma unroll
            for (int nt = 0; nt < 8; nt++) {
                int r = wn * 64 + nt * 8 + gid;
                uint2 bv = *(const uint2*)&bs[r * GST + ko];
                uint32_t b[2] = { bv.x, bv.y };
                mma_tf32(acc[0][nt], a[0], b);
                mma_tf32(acc[1][nt], a[1], b);
            }
        }
    }

    #pragma unroll
    for (int mt = 0; mt < 2; mt++) {
        #pragma unroll
        for (int nt = 0; nt < 8; nt++) {
            int r1 = bm + wm * 32 + mt * 16 + gid;
            int r2 = r1 + 8;
            int n0 = bn + wn * 64 + nt * 8 + 2 * tig;
            if (MODE == 0) {
                *(float2*)&Cm[(long)r1 * C_ + n0] = make_float2(acc[mt][nt][0], acc[mt][nt][1]);
                *(float2*)&Cm[(long)r2 * C_ + n0] = make_float2(acc[mt][nt][2], acc[mt][nt][3]);
            } else {
                int w  = n0 >> 10;          // 0=Q, 1=K, 2=V
                int nc = n0 & 1023;
                if (w == 2) {
                    *(float2*)&Cv[(long)r1 * C_ + nc] = make_float2(acc[mt][nt][0], acc[mt][nt][1]);
                    *(float2*)&Cv[(long)r2 * C_ + nc] = make_float2(acc[mt][nt][2], acc[mt][nt][3]);
                } else {
                    float* dst = (w == 0) ? Cq : Ck;
                    int na = (nc & ~7) | perm8(nc & 7);
                    int nb = ((nc + 1) & ~7) | perm8((nc + 1) & 7);
                    dst[(long)r1 * C_ + na] = tf32r(acc[mt][nt][0]);
                    dst[(long)r1 * C_ + nb] = tf32r(acc[mt][nt][1]);
                    dst[(long)r2 * C_ + na] = tf32r(acc[mt][nt][2]);
                    dst[(long)r2 * C_ + nb] = tf32r(acc[mt][nt][3]);
                }
            }
        }
    }
}

// ---------------------------------------------------------------------------
// V transpose: g_Vt[((b*16+h)*64+d)][t0+perm(tx)] = tf32r(V[t0+tx][h*64+d])
// ---------------------------------------------------------------------------
__global__ void vtrans()
{
    __shared__ float tile[32][33];
    const int t0 = blockIdx.x * 32, c0 = blockIdx.y * 32, b = blockIdx.z;
    const int tx = threadIdx.x, ty = threadIdx.y;

    #pragma unroll
    for (int r = 0; r < 4; r++) {
        int t = ty + r * 8;
        tile[t][tx] = g_V[(long)(b * T_ + t0 + t) * C_ + c0 + tx];
    }
    __syncthreads();

    const int txp = (tx & ~7) | perm8(tx & 7);
    #pragma unroll
    for (int r = 0; r < 4; r++) {
        int cc = c0 + ty + r * 8;
        int h = cc >> 6, d = cc & 63;
        g_Vt[(long)(((b << 4) + h) * 64 + d) * T_ + t0 + txp] =
            tf32r(tile[tx][ty + r * 8]);
    }
}

// ---------------------------------------------------------------------------
// Flash attention (causal), tf32 mma. BQ=128: grid (16, 32), 256 thr = 8 warps.
// Double-buffered 64-row KV tiles; ONE barrier per tile; P kept in REGISTERS
// (C-frag -> A-frag via intra-quad shuffles, no smem round trip).
// smem: Q[128][68] + K[2][64][68] + V[2][64][68] = 102KB -> 2 CTAs/SM.
// ---------------------------------------------------------------------------
#define AST 68
#define QROWS 128
#define ATILE64 (64 * AST)
#define ATTN_SMEM ((QROWS + 4 * 64) * AST * 4)

__global__ void __launch_bounds__(256, 2)
attn_tc()
{
    extern __shared__ float sh[];
    float* Qs  = sh;                              // [128][AST]
    float* Kst = sh + QROWS * AST;                // 2 stages
    float* Vst = sh + QROWS * AST + 2 * ATILE64;  // 2 stages

    const int qb = gridDim.x - 1 - blockIdx.x;    // big tiles first
    const int bh = blockIdx.y, bb = bh >> 4, h = bh & 15;
    const int tid = threadIdx.x, lane = tid & 31, warp = tid >> 5;
    const int gid = lane >> 2, tig = lane & 3;
    const int m0 = warp * 16;
    const int ko2 = 2 * tig;
    const int pe = perm8(2 * tig), po = perm8(2 * tig + 1);
    const int srcA = (lane & 0x1C) | (tig >> 1);  // shuffle source lanes
    const int srcB = srcA + 2;
    const bool oddt = tig & 1;

    const long kbase0 = ((long)(bb * T_)) * C_ + h * 64;
    const long vbase0 = ((long)((bb * 16 + h) * 64)) * T_;

    auto load_kv = [&](int kb, int s) {
        float* Ks = Kst + s * ATILE64;
        float* Vs = Vst + s * ATILE64;
        const long kbase = kbase0 + (long)(kb * 64) * C_;
        const long vbase = vbase0 + kb * 64;
        #pragma unroll
        for (int j = 0; j < 4; j++) {
            int c = tid + j * 256;
            int row = c >> 4, ch = (c & 15) << 2;
            cpa16(s2u(&Ks[row * AST + ch]), &g_K [kbase + (long)row * C_ + ch]);
            cpa16(s2u(&Vs[row * AST + ch]), &g_Vt[vbase + (long)row * T_ + ch]);
        }
    };

    // Prologue: Q (128 rows) + KV tile 0.
    #pragma unroll
    for (int j = 0; j < 8; j++) {
        int c = tid + j * 256;
        int row = c >> 4, ch = (c & 15) << 2;
        cpa16(s2u(&Qs[row * AST + ch]),
              &g_Q[kbase0 + (long)(qb * 128 + row) * C_ + ch]);
    }
    load_kv(0, 0);
    CPCOMMIT();

    float mr0 = -INFINITY, mr1 = -INFINITY, l0 = 0.f, l1 = 0.f;
    float oacc[8][4];
    #pragma unroll
    for (int nt = 0; nt < 8; nt++)
        #pragma unroll
        for (int e = 0; e < 4; e++) oacc[nt][e] = 0.f;

    const int nkb = 2 * qb + 2;
    for (int kb = 0; kb < nkb; kb++) {
        const int s = kb & 1;
        float* Ks = Kst + s * ATILE64;
        float* Vs = Vst + s * ATILE64;

        CPWAIT0();
        __syncthreads();   // tile kb resident; all warps past tile kb-1
        if (kb + 1 < nkb) { load_kv(kb + 1, s ^ 1); CPCOMMIT(); }

        // Fully masked warp-tile (warps 0-3 on last diagonal tile): skip.
        if (kb == nkb - 1 && m0 < 64) continue;

        // ---- S = Q @ K^T ----
        float sacc[8][4];
        #pragma unroll
        for (int nt = 0; nt < 8; nt++)
            #pragma unroll
            for (int e = 0; e < 4; e++) sacc[nt][e] = 0.f;

        #pragma unroll
        for (int ks = 0; ks < 8; ks++) {
            int ko = ks * 8 + ko2;
            uint2 lo = *(const uint2*)&Qs[(m0 + gid) * AST + ko];
            uint2 hi = *(const uint2*)&Qs[(m0 + 8 + gid) * AST + ko];
            uint32_t a[4] = { lo.x, hi.x, lo.y, hi.y };
            #pragma unroll
            for (int nt = 0; nt < 8; nt++) {
                uint2 bv = *(const uint2*)&Ks[(nt * 8 + gid) * AST + ko];
                uint32_t b[2] = { bv.x, bv.y };
                mma_tf32(sacc[nt], a, b);
            }
        }

        // ---- softmax (log2 domain) ----
        const int dd = (kb - 2 * qb) * 64;   // diagonal column offset
        const bool diag = (kb >= 2 * qb);
        float mx0 = -INFINITY, mx1 = -INFINITY;
        #pragma unroll
        for (int nt = 0; nt < 8; nt++) {
            #pragma unroll
            for (int e = 0; e < 4; e++) {
                float sv = sacc[nt][e] * K2L;
                if (diag) {
                    int rl = m0 + gid + ((e >> 1) << 3);
                    int cl = nt * 8 + 2 * tig + (e & 1);
                    if (cl + dd > rl) sv = -INFINITY;
                }
                sacc[nt][e] = sv;
            }
            mx0 = fmaxf(mx0, fmaxf(sacc[nt][0], sacc[nt][1]));
            mx1 = fmaxf(mx1, fmaxf(sacc[nt][2], sacc[nt][3]));
        }
        mx0 = fmaxf(mx0, __shfl_xor_sync(~0u, mx0, 1));
        mx0 = fmaxf(mx0, __shfl_xor_sync(~0u, mx0, 2));
        mx1 = fmaxf(mx1, __shfl_xor_sync(~0u, mx1, 1));
        mx1 = fmaxf(mx1, __shfl_xor_sync(~0u, mx1, 2));
        float mn0 = fmaxf(mr0, mx0), mn1 = fmaxf(mr1, mx1);
        float al0 = ex2f(mr0 - mn0), al1 = ex2f(mr1 - mn1);
        float rs0 = 0.f, rs1 = 0.f;
        #pragma unroll
        for (int nt = 0; nt < 8; nt++) {
            sacc[nt][0] = ex2f(sacc[nt][0] - mn0); rs0 += sacc[nt][0];
            sacc[nt][1] = ex2f(sacc[nt][1] - mn0); rs0 += sacc[nt][1];
            sacc[nt][2] = ex2f(sacc[nt][2] - mn1); rs1 += sacc[nt][2];
            sacc[nt][3] = ex2f(sacc[nt][3] - mn1); rs1 += sacc[nt][3];
        }
        rs0 += __shfl_xor_sync(~0u, rs0, 1);
        rs0 += __shfl_xor_sync(~0u, rs0, 2);
        rs1 += __shfl_xor_sync(~0u, rs1, 1);
        rs1 += __shfl_xor_sync(~0u, rs1, 2);
        l0 = l0 * al0 + rs0;  l1 = l1 * al1 + rs1;
        mr0 = mn0;  mr1 = mn1;
        #pragma unroll
        for (int nt = 0; nt < 8; nt++) {
            oacc[nt][0] *= al0; oacc[nt][1] *= al0;
            oacc[nt][2] *= al1; oacc[nt][3] *= al1;
        }

        // ---- C-frag -> A-frag in registers (intra-quad shuffles) ----
        #pragma unroll
        for (int nt = 0; nt < 8; nt++) {
            float p0 = sacc[nt][0], p1 = sacc[nt][1];
            float p2 = sacc[nt][2], p3 = sacc[nt][3];
            float u0 = __shfl_sync(~0u, p0, srcA), u1 = __shfl_sync(~0u, p1, srcA);
            float v0 = __shfl_sync(~0u, p0, srcB), v1 = __shfl_sync(~0u, p1, srcB);
            float w0 = __shfl_sync(~0u, p2, srcA), w1 = __shfl_sync(~0u, p3, srcA);
            float x0 = __shfl_sync(~0u, p2, srcB), x1 = __shfl_sync(~0u, p3, srcB);
            sacc[nt][0] = tf32r(oddt ? u1 : u0);   // row g,   col t
            sacc[nt][1] = tf32r(oddt ? w1 : w0);   // row g+8, col t
            sacc[nt][2] = tf32r(oddt ? v1 : v0);   // row g,   col t+4
            sacc[nt][3] = tf32r(oddt ? x1 : x0);   // row g+8, col t+4
        }

        // ---- O += P @ V ----
        #pragma unroll
        for (int ks = 0; ks < 8; ks++) {
            const uint32_t* a = (const uint32_t*)sacc[ks];
            #pragma unroll
            for (int nt = 0; nt < 8; nt++) {
                uint2 bv = *(const uint2*)&Vs[(nt * 8 + gid) * AST + ks * 8 + ko2];
                uint32_t b[2] = { bv.x, bv.y };
                mma_tf32(oacc[nt], a, b);
            }
        }
    }

    // ---- finalize: AO rounded + permuted for O-projection GEMM ----
    float inv0 = 1.f / l0, inv1 = 1.f / l1;
    long base = ((long)(bb * T_ + qb * 128 + m0 + gid)) * C_ + h * 64;
    #pragma unroll
    for (int nt = 0; nt < 8; nt++) {
        g_AO[base + nt * 8 + pe]           = tf32r(oacc[nt][0] * inv0);
        g_AO[base + nt * 8 + po]           = tf32r(oacc[nt][1] * inv0);
        g_AO[base + 8L * C_ + nt * 8 + pe] = tf32r(oacc[nt][2] * inv1);
        g_AO[base + 8L * C_ + nt * 8 + po] = tf32r(oacc[nt][3] * inv1);
    }
}

// ---------------------------------------------------------------------------
extern "C" void kernel_launch(void* const* d_in, const int* in_sizes, int n_in,
                              void* d_out, int out_size)
{
    const float* x  = (const float*)d_in[0];
    const float* Wq = (const float*)d_in[1];
    const float* Wk = (const float*)d_in[2];
    const float* Wv = (const float*)d_in[3];
    const float* Wo = (const float*)d_in[4];
    float* out = (float*)d_out;

    float *xr, *Wr, *Q, *K, *V, *Vt, *AO;
    cudaGetSymbolAddress((void**)&xr, g_xr);
    cudaGetSymbolAddress((void**)&Wr, g_Wr);
    cudaGetSymbolAddress((void**)&Q,  g_Q);
    cudaGetSymbolAddress((void**)&K,  g_K);
    cudaGetSymbolAddress((void**)&V,  g_V);
    cudaGetSymbolAddress((void**)&Vt, g_Vt);
    cudaGetSymbolAddress((void**)&AO, g_AO);

    cudaFuncSetAttribute(gemm_tc<0>, cudaFuncAttributeMaxDynamicSharedMemorySize, GEMM_SMEM);
    cudaFuncSetAttribute(gemm_tc<3>, cudaFuncAttributeMaxDynamicSharedMemorySize, GEMM_SMEM);
    cudaFuncSetAttribute(attn_tc,    cudaFuncAttributeMaxDynamicSharedMemorySize, ATTN_SMEM);

    prep_x<<<2048, 256>>>(x, xr);
    prep_w<<<dim3(512, 4), 256>>>(Wq, Wk, Wv, Wo, Wr);

    // Fused QKV projection: B = [Wq; Wk; Wv] rows 0..3071 of g_Wr.
    gemm_tc<3><<<dim3(24, 32), 256, GEMM_SMEM>>>(xr, Wr, nullptr, Q, K, V);

    vtrans<<<dim3(T_ / 32, C_ / 32, B_), dim3(32, 8)>>>();

    attn_tc<<<dim3(T_ / 128, B_ * H_), 256, ATTN_SMEM>>>();

    gemm_tc<0><<<dim3(8, 32), 256, GEMM_SMEM>>>(AO, Wr + 3L * C_ * C_, out,
                                                nullptr, nullptr, nullptr);
}

// round 13
// speedup vs baseline: 1.1301x; 1.1301x over previous
#include <cuda_runtime.h>
#include <math.h>
#include <stdint.h>

#define B_ 2
#define T_ 2048
#define C_ 1024
#define H_ 16
#define D_ 64
#define M_ 4096
#define K2L 0.18033688f   // 0.125 * log2(e)

// Scratch (allocation-free)
__device__ float g_xr[M_*C_];
__device__ float g_Wr[4][C_*C_];
__device__ float g_Q [M_*C_];
__device__ float g_K [M_*C_];
__device__ float g_V [M_*C_];
__device__ float g_Vt[B_*H_*D_*T_];
__device__ float g_AO[M_*C_];

// ---------------------------------------------------------------------------
__device__ __forceinline__ float tf32r(float x) {
    uint32_t u; asm("cvt.rna.tf32.f32 %0, %1;" : "=r"(u) : "f"(x));
    return __uint_as_float(u);
}
__host__ __device__ __forceinline__ int perm8(int k) { return ((k & 3) << 1) | (k >> 2); }
__device__ __forceinline__ uint32_t s2u(const void* p) {
    return (uint32_t)__cvta_generic_to_shared(p);
}
__device__ __forceinline__ void cpa16(uint32_t d, const void* s) {
    asm volatile("cp.async.cg.shared.global [%0], [%1], 16;\n" :: "r"(d), "l"(s));
}
#define CPCOMMIT() asm volatile("cp.async.commit_group;\n")
#define CPWAIT0()  asm volatile("cp.async.wait_group 0;\n")
__device__ __forceinline__ float ex2f(float x) {
    float y; asm("ex2.approx.ftz.f32 %0, %1;" : "=f"(y) : "f"(x)); return y;
}
__device__ __forceinline__ void mma_tf32(float* c, const uint32_t* a, const uint32_t* b) {
    asm volatile(
        "mma.sync.aligned.m16n8k8.row.col.f32.tf32.tf32.f32 "
        "{%0,%1,%2,%3}, {%4,%5,%6,%7}, {%8,%9}, {%0,%1,%2,%3};\n"
        : "+f"(c[0]), "+f"(c[1]), "+f"(c[2]), "+f"(c[3])
        : "r"(a[0]), "r"(a[1]), "r"(a[2]), "r"(a[3]), "r"(b[0]), "r"(b[1]));
}

// ---------------------------------------------------------------------------
// Prepass: round to tf32 + permute k within 8-groups (two float4 stores).
// ---------------------------------------------------------------------------
__device__ __forceinline__ void prep8(const float* __restrict__ s, float* __restrict__ d) {
    float4 a = *(const float4*)(s);
    float4 b = *(const float4*)(s + 4);
    *(float4*)(d)     = make_float4(tf32r(a.x), tf32r(b.x), tf32r(a.y), tf32r(b.y));
    *(float4*)(d + 4) = make_float4(tf32r(a.z), tf32r(b.z), tf32r(a.w), tf32r(b.w));
}
__global__ void prep_x(const float* __restrict__ src, float* __restrict__ dst) {
    int i = (blockIdx.x * blockDim.x + threadIdx.x) * 8;
    prep8(src + i, dst + i);
}
__global__ void prep_w(const float* w0, const float* w1, const float* w2,
                       const float* w3, float* __restrict__ dst) {
    const float* src = (blockIdx.y == 0) ? w0 : (blockIdx.y == 1) ? w1
                     : (blockIdx.y == 2) ? w2 : w3;
    float* d = dst + (long)blockIdx.y * C_ * C_;
    int i = (blockIdx.x * blockDim.x + threadIdx.x) * 8;
    prep8(src + i, d + i);
}

// ---------------------------------------------------------------------------
// GEMM-NT (tf32 mma.sync): validated 120 TF/s pipeline.
// MODE 0: plain fp32 out. MODE 3: fused QKV epilogue.
// ---------------------------------------------------------------------------
#define GST 36
#define GEMM_SMEM (4 * 128 * GST * 4)

template<int MODE>
__global__ void __launch_bounds__(256)
gemm_tc(const float* __restrict__ A, const float* __restrict__ Bm,
        float* __restrict__ Cm, float* __restrict__ Cq,
        float* __restrict__ Ck, float* __restrict__ Cv)
{
    extern __shared__ float sh[];
    float* As = sh;
    float* Bs = sh + 2 * 128 * GST;

    const int tid = threadIdx.x, lane = tid & 31, warp = tid >> 5;
    const int gid = lane >> 2, tig = lane & 3;
    const int wm = warp & 3, wn = warp >> 2;
    const int bm = blockIdx.y * 128, bn = blockIdx.x * 128;
    const int frow = tid >> 3, fcol = (tid & 7) << 2;
    const int ko2 = 2 * tig;

    float acc[2][8][4];
    #pragma unroll
    for (int mt = 0; mt < 2; mt++)
        #pragma unroll
        for (int nt = 0; nt < 8; nt++)
            #pragma unroll
            for (int e = 0; e < 4; e++) acc[mt][nt][e] = 0.f;

    auto loadst = [&](int s, int kt) {
        #pragma unroll
        for (int p = 0; p < 4; p++) {
            int row = frow + p * 32;
            cpa16(s2u(&As[(s * 128 + row) * GST + fcol]),
                  &A[(long)(bm + row) * C_ + kt + fcol]);
            cpa16(s2u(&Bs[(s * 128 + row) * GST + fcol]),
                  &Bm[(long)(bn + row) * C_ + kt + fcol]);
        }
    };

    loadst(0, 0); CPCOMMIT();

    #pragma unroll 2
    for (int t = 0; t < 32; t++) {
        CPWAIT0(); __syncthreads();
        if (t + 1 < 32) { loadst((t + 1) & 1, (t + 1) * 32); CPCOMMIT(); }
        const float* as = As + (t & 1) * 128 * GST;
        const float* bs = Bs + (t & 1) * 128 * GST;
        #pragma unroll
        for (int ks = 0; ks < 4; ks++) {
            int ko = ks * 8 + ko2;
            uint32_t a[2][4];
            #pragma unroll
            for (int mt = 0; mt < 2; mt++) {
                int r = wm * 32 + mt * 16 + gid;
                uint2 lo = *(const uint2*)&as[r * GST + ko];
                uint2 hi = *(const uint2*)&as[(r + 8) * GST + ko];
                a[mt][0] = lo.x; a[mt][1] = hi.x; a[mt][2] = lo.y; a[mt][3] = hi.y;
            }
            #pragma unroll
            for (int nt = 0; nt < 8; nt++) {
                int r = wn * 64 + nt * 8 + gid;
                uint2 bv = *(const uint2*)&bs[r * GST + ko];
                uint32_t b[2] = { bv.x, bv.y };
                mma_tf32(acc[0][nt], a[0], b);
                mma_tf32(acc[1][nt], a[1], b);
            }
        }
    }

    #pragma unroll
    for (int mt = 0; mt < 2; mt++) {
        #pragma unroll
        for (int nt = 0; nt < 8; nt++) {
            int r1 = bm + wm * 32 + mt * 16 + gid;
            int r2 = r1 + 8;
            int n0 = bn + wn * 64 + nt * 8 + 2 * tig;
            if (MODE == 0) {
                *(float2*)&Cm[(long)r1 * C_ + n0] = make_float2(acc[mt][nt][0], acc[mt][nt][1]);
                *(float2*)&Cm[(long)r2 * C_ + n0] = make_float2(acc[mt][nt][2], acc[mt][nt][3]);
            } else {
                int w  = n0 >> 10;          // 0=Q, 1=K, 2=V
                int nc = n0 & 1023;
                if (w == 2) {
                    *(float2*)&Cv[(long)r1 * C_ + nc] = make_float2(acc[mt][nt][0], acc[mt][nt][1]);
                    *(float2*)&Cv[(long)r2 * C_ + nc] = make_float2(acc[mt][nt][2], acc[mt][nt][3]);
                } else {
                    float* dst = (w == 0) ? Cq : Ck;
                    int na = (nc & ~7) | perm8(nc & 7);
                    int nb = ((nc + 1) & ~7) | perm8((nc + 1) & 7);
                    dst[(long)r1 * C_ + na] = tf32r(acc[mt][nt][0]);
                    dst[(long)r1 * C_ + nb] = tf32r(acc[mt][nt][1]);
                    dst[(long)r2 * C_ + na] = tf32r(acc[mt][nt][2]);
                    dst[(long)r2 * C_ + nb] = tf32r(acc[mt][nt][3]);
                }
            }
        }
    }
}

// ---------------------------------------------------------------------------
// V transpose: g_Vt[((b*16+h)*64+d)][t0+perm(tx)] = tf32r(V[t0+tx][h*64+d])
// ---------------------------------------------------------------------------
__global__ void vtrans()
{
    __shared__ float tile[32][33];
    const int t0 = blockIdx.x * 32, c0 = blockIdx.y * 32, b = blockIdx.z;
    const int tx = threadIdx.x, ty = threadIdx.y;

    #pragma unroll
    for (int r = 0; r < 4; r++) {
        int t = ty + r * 8;
        tile[t][tx] = g_V[(long)(b * T_ + t0 + t) * C_ + c0 + tx];
    }
    __syncthreads();

    const int txp = (tx & ~7) | perm8(tx & 7);
    #pragma unroll
    for (int r = 0; r < 4; r++) {
        int cc = c0 + ty + r * 8;
        int h = cc >> 6, d = cc & 63;
        g_Vt[(long)(((b << 4) + h) * 64 + d) * T_ + t0 + txp] =
            tf32r(tile[tx][ty + r * 8]);
    }
}

// ---------------------------------------------------------------------------
// Flash attention (causal), tf32 mma. BQ=128: grid (16, 32), 128 thr = 4 warps.
// Each warp owns 32 q-rows (two m16 strips) -> every K/V B-fragment feeds 2
// mmas (smem traffic per mma cut 40%). Double-buffered KV, register-resident P
// (validated shuffle conversion), one barrier per tile. No launch_bounds cap
// on regs (<=255): no spills; 2 CTAs/SM by smem (102KB).
// ---------------------------------------------------------------------------
#define AST 68
#define QROWS 128
#define ATILE64 (64 * AST)
#define ATTN_SMEM ((QROWS + 4 * 64) * AST * 4)

__global__ void __launch_bounds__(128)
attn_tc()
{
    extern __shared__ float sh[];
    float* Qs  = sh;                              // [128][AST]
    float* Kst = sh + QROWS * AST;                // 2 stages
    float* Vst = sh + QROWS * AST + 2 * ATILE64;  // 2 stages

    const int qb = gridDim.x - 1 - blockIdx.x;    // big tiles first
    const int bh = blockIdx.y, bb = bh >> 4, h = bh & 15;
    const int tid = threadIdx.x, lane = tid & 31, warp = tid >> 5;
    const int gid = lane >> 2, tig = lane & 3;
    const int m0 = warp * 32;                     // warp's first q row (of 32)
    const int ko2 = 2 * tig;
    const int pe = perm8(2 * tig), po = perm8(2 * tig + 1);
    const int srcA = (lane & 0x1C) | (tig >> 1);  // shuffle source lanes
    const int srcB = srcA + 2;
    const bool oddt = tig & 1;

    const long kbase0 = ((long)(bb * T_)) * C_ + h * 64;
    const long vbase0 = ((long)((bb * 16 + h) * 64)) * T_;

    auto load_kv = [&](int kb, int s) {
        float* Ks = Kst + s * ATILE64;
        float* Vs = Vst + s * ATILE64;
        const long kbase = kbase0 + (long)(kb * 64) * C_;
        const long vbase = vbase0 + kb * 64;
        #pragma unroll
        for (int j = 0; j < 8; j++) {
            int c = tid + j * 128;
            int row = c >> 4, ch = (c & 15) << 2;
            cpa16(s2u(&Ks[row * AST + ch]), &g_K [kbase + (long)row * C_ + ch]);
            cpa16(s2u(&Vs[row * AST + ch]), &g_Vt[vbase + (long)row * T_ + ch]);
        }
    };

    // Prologue: Q (128 rows) + KV tile 0.
    #pragma unroll
    for (int j = 0; j < 16; j++) {
        int c = tid + j * 128;
        int row = c >> 4, ch = (c & 15) << 2;
        cpa16(s2u(&Qs[row * AST + ch]),
              &g_Q[kbase0 + (long)(qb * 128 + row) * C_ + ch]);
    }
    load_kv(0, 0);
    CPCOMMIT();

    float mr[2][2], lsum[2][2];
    #pragma unroll
    for (int mt = 0; mt < 2; mt++) {
        mr[mt][0] = -INFINITY; mr[mt][1] = -INFINITY;
        lsum[mt][0] = 0.f;     lsum[mt][1] = 0.f;
    }
    float oacc[2][8][4];
    #pragma unroll
    for (int mt = 0; mt < 2; mt++)
        #pragma unroll
        for (int nt = 0; nt < 8; nt++)
            #pragma unroll
            for (int e = 0; e < 4; e++) oacc[mt][nt][e] = 0.f;

    const int nkb = 2 * qb + 2;
    for (int kb = 0; kb < nkb; kb++) {
        const int s = kb & 1;
        float* Ks = Kst + s * ATILE64;
        float* Vs = Vst + s * ATILE64;

        CPWAIT0();
        __syncthreads();   // tile kb resident; all warps past tile kb-1
        if (kb + 1 < nkb) { load_kv(kb + 1, s ^ 1); CPCOMMIT(); }

        // Fully masked warp-tile (warps 0-1 on last diagonal tile): skip.
        if (kb == nkb - 1 && m0 < 64) continue;

        // ---- S = Q @ K^T ----
        float sacc[2][8][4];
        #pragma unroll
        for (int mt = 0; mt < 2; mt++)
            #pragma unroll
            for (int nt = 0; nt < 8; nt++)
                #pragma unroll
                for (int e = 0; e < 4; e++) sacc[mt][nt][e] = 0.f;

        #pragma unroll
        for (int ks = 0; ks < 8; ks++) {
            int ko = ks * 8 + ko2;
            uint32_t a[2][4];
            #pragma unroll
            for (int mt = 0; mt < 2; mt++) {
                int r = m0 + mt * 16 + gid;
                uint2 lo = *(const uint2*)&Qs[r * AST + ko];
                uint2 hi = *(const uint2*)&Qs[(r + 8) * AST + ko];
                a[mt][0] = lo.x; a[mt][1] = hi.x; a[mt][2] = lo.y; a[mt][3] = hi.y;
            }
            #pragma unroll
            for (int nt = 0; nt < 8; nt++) {
                uint2 bv = *(const uint2*)&Ks[(nt * 8 + gid) * AST + ko];
                uint32_t b[2] = { bv.x, bv.y };
                mma_tf32(sacc[0][nt], a[0], b);
                mma_tf32(sacc[1][nt], a[1], b);
            }
        }

        // ---- softmax (log2 domain) per m16 strip ----
        const int dd = (kb - 2 * qb) * 64;   // diagonal column offset
        const bool diag = (kb >= 2 * qb);
        #pragma unroll
        for (int mt = 0; mt < 2; mt++) {
            float mx0 = -INFINITY, mx1 = -INFINITY;
            #pragma unroll
            for (int nt = 0; nt < 8; nt++) {
                #pragma unroll
                for (int e = 0; e < 4; e++) {
                    float sv = sacc[mt][nt][e] * K2L;
                    if (diag) {
                        int rl = m0 + mt * 16 + gid + ((e >> 1) << 3);
                        int cl = nt * 8 + 2 * tig + (e & 1);
                        if (cl + dd > rl) sv = -INFINITY;
                    }
                    sacc[mt][nt][e] = sv;
                }
                mx0 = fmaxf(mx0, fmaxf(sacc[mt][nt][0], sacc[mt][nt][1]));
                mx1 = fmaxf(mx1, fmaxf(sacc[mt][nt][2], sacc[mt][nt][3]));
            }
            mx0 = fmaxf(mx0, __shfl_xor_sync(~0u, mx0, 1));
            mx0 = fmaxf(mx0, __shfl_xor_sync(~0u, mx0, 2));
            mx1 = fmaxf(mx1, __shfl_xor_sync(~0u, mx1, 1));
            mx1 = fmaxf(mx1, __shfl_xor_sync(~0u, mx1, 2));
            float mn0 = fmaxf(mr[mt][0], mx0), mn1 = fmaxf(mr[mt][1], mx1);
            float al0 = ex2f(mr[mt][0] - mn0), al1 = ex2f(mr[mt][1] - mn1);
            float rs0 = 0.f, rs1 = 0.f;
            #pragma unroll
            for (int nt = 0; nt < 8; nt++) {
                sacc[mt][nt][0] = ex2f(sacc[mt][nt][0] - mn0); rs0 += sacc[mt][nt][0];
                sacc[mt][nt][1] = ex2f(sacc[mt][nt][1] - mn0); rs0 += sacc[mt][nt][1];
                sacc[mt][nt][2] = ex2f(sacc[mt][nt][2] - mn1); rs1 += sacc[mt][nt][2];
                sacc[mt][nt][3] = ex2f(sacc[mt][nt][3] - mn1); rs1 += sacc[mt][nt][3];
            }
            rs0 += __shfl_xor_sync(~0u, rs0, 1);
            rs0 += __shfl_xor_sync(~0u, rs0, 2);
            rs1 += __shfl_xor_sync(~0u, rs1, 1);
            rs1 += __shfl_xor_sync(~0u, rs1, 2);
            lsum[mt][0] = lsum[mt][0] * al0 + rs0;
            lsum[mt][1] = lsum[mt][1] * al1 + rs1;
            mr[mt][0] = mn0;  mr[mt][1] = mn1;
            #pragma unroll
            for (int nt = 0; nt < 8; nt++) {
                oacc[mt][nt][0] *= al0; oacc[mt][nt][1] *= al0;
                oacc[mt][nt][2] *= al1; oacc[mt][nt][3] *= al1;
            }

            // ---- C-frag -> A-frag in registers (validated shuffle mapping) ----
            #pragma unroll
            for (int nt = 0; nt < 8; nt++) {
                float p0 = sacc[mt][nt][0], p1 = sacc[mt][nt][1];
                float p2 = sacc[mt][nt][2], p3 = sacc[mt][nt][3];
                float u0 = __shfl_sync(~0u, p0, srcA), u1 = __shfl_sync(~0u, p1, srcA);
                float v0 = __shfl_sync(~0u, p0, srcB), v1 = __shfl_sync(~0u, p1, srcB);
                float w0 = __shfl_sync(~0u, p2, srcA), w1 = __shfl_sync(~0u, p3, srcA);
                float x0 = __shfl_sync(~0u, p2, srcB), x1 = __shfl_sync(~0u, p3, srcB);
                sacc[mt][nt][0] = tf32r(oddt ? u1 : u0);   // row g,   col t
                sacc[mt][nt][1] = tf32r(oddt ? w1 : w0);   // row g+8, col t
                sacc[mt][nt][2] = tf32r(oddt ? v1 : v0);   // row g,   col t+4
                sacc[mt][nt][3] = tf32r(oddt ? x1 : x0);   // row g+8, col t+4
            }
        }

        // ---- O += P @ V (B-frag shared across both m-strips) ----
        #pragma unroll
        for (int ks = 0; ks < 8; ks++) {
            const uint32_t* a0 = (const uint32_t*)sacc[0][ks];
            const uint32_t* a1 = (const uint32_t*)sacc[1][ks];
            #pragma unroll
            for (int nt = 0; nt < 8; nt++) {
                uint2 bv = *(const uint2*)&Vs[(nt * 8 + gid) * AST + ks * 8 + ko2];
                uint32_t b[2] = { bv.x, bv.y };
                mma_tf32(oacc[0][nt], a0, b);
                mma_tf32(oacc[1][nt], a1, b);
            }
        }
    }

    // ---- finalize: AO rounded + permuted for O-projection GEMM ----
    #pragma unroll
    for (int mt = 0; mt < 2; mt++) {
        float inv0 = 1.f / lsum[mt][0], inv1 = 1.f / lsum[mt][1];
        long base = ((long)(bb * T_ + qb * 128 + m0 + mt * 16 + gid)) * C_ + h * 64;
        #pragma unroll
        for (int nt = 0; nt < 8; nt++) {
            g_AO[base + nt * 8 + pe]           = tf32r(oacc[mt][nt][0] * inv0);
            g_AO[base + nt * 8 + po]           = tf32r(oacc[mt][nt][1] * inv0);
            g_AO[base + 8L * C_ + nt * 8 + pe] = tf32r(oacc[mt][nt][2] * inv1);
            g_AO[base + 8L * C_ + nt * 8 + po] = tf32r(oacc[mt][nt][3] * inv1);
        }
    }
}

// ---------------------------------------------------------------------------
extern "C" void kernel_launch(void* const* d_in, const int* in_sizes, int n_in,
                              void* d_out, int out_size)
{
    const float* x  = (const float*)d_in[0];
    const float* Wq = (const float*)d_in[1];
    const float* Wk = (const float*)d_in[2];
    const float* Wv = (const float*)d_in[3];
    const float* Wo = (const float*)d_in[4];
    float* out = (float*)d_out;

    float *xr, *Wr, *Q, *K, *V, *Vt, *AO;
    cudaGetSymbolAddress((void**)&xr, g_xr);
    cudaGetSymbolAddress((void**)&Wr, g_Wr);
    cudaGetSymbolAddress((void**)&Q,  g_Q);
    cudaGetSymbolAddress((void**)&K,  g_K);
    cudaGetSymbolAddress((void**)&V,  g_V);
    cudaGetSymbolAddress((void**)&Vt, g_Vt);
    cudaGetSymbolAddress((void**)&AO, g_AO);

    cudaFuncSetAttribute(gemm_tc<0>, cudaFuncAttributeMaxDynamicSharedMemorySize, GEMM_SMEM);
    cudaFuncSetAttribute(gemm_tc<3>, cudaFuncAttributeMaxDynamicSharedMemorySize, GEMM_SMEM);
    cudaFuncSetAttribute(attn_tc,    cudaFuncAttributeMaxDynamicSharedMemorySize, ATTN_SMEM);

    prep_x<<<2048, 256>>>(x, xr);
    prep_w<<<dim3(512, 4), 256>>>(Wq, Wk, Wv, Wo, Wr);

    // Fused QKV projection: B = [Wq; Wk; Wv] rows 0..3071 of g_Wr.
    gemm_tc<3><<<dim3(24, 32), 256, GEMM_SMEM>>>(xr, Wr, nullptr, Q, K, V);

    vtrans<<<dim3(T_ / 32, C_ / 32, B_), dim3(32, 8)>>>();

    attn_tc<<<dim3(T_ / 128, B_ * H_), 128, ATTN_SMEM>>>();

    gemm_tc<0><<<dim3(8, 32), 256, GEMM_SMEM>>>(AO, Wr + 3L * C_ * C_, out,
                                                nullptr, nullptr, nullptr);
}

// round 14
// speedup vs baseline: 2.3028x; 2.0377x over previous
#include <cuda_runtime.h>
#include <cuda_fp16.h>
#include <math.h>
#include <stdint.h>

#define B_ 2
#define T_ 2048
#define C_ 1024
#define H_ 16
#define D_ 64
#define M_ 4096
#define K2L 0.18033688f   // 0.125 * log2(e)

// Scratch (allocation-free), all fp16
__device__ __half g_xh[M_*C_];
__device__ __half g_Wh[4*C_*C_];
__device__ __half g_Q [M_*C_];
__device__ __half g_K [M_*C_];
__device__ __half g_V [M_*C_];
__device__ __half g_Vt[B_*H_*D_*T_];
__device__ __half g_AO[M_*C_];

// ---------------------------------------------------------------------------
__device__ __forceinline__ uint32_t s2u(const void* p) {
    return (uint32_t)__cvta_generic_to_shared(p);
}
__device__ __forceinline__ void cpa16(uint32_t d, const void* s) {
    asm volatile("cp.async.cg.shared.global [%0], [%1], 16;\n" :: "r"(d), "l"(s));
}
#define CPCOMMIT() asm volatile("cp.async.commit_group;\n")
#define CPWAIT0()  asm volatile("cp.async.wait_group 0;\n")
__device__ __forceinline__ float ex2f(float x) {
    float y; asm("ex2.approx.ftz.f32 %0, %1;" : "=f"(y) : "f"(x)); return y;
}
__device__ __forceinline__ uint32_t packh(float lo, float hi) {
    __half2 h = __floats2half2_rn(lo, hi);
    return *(uint32_t*)&h;
}
// fp16 m16n8k16, fp32 accumulate
__device__ __forceinline__ void mma_f16(float* c, const uint32_t* a, const uint32_t* b) {
    asm volatile(
        "mma.sync.aligned.m16n8k16.row.col.f32.f16.f16.f32 "
        "{%0,%1,%2,%3}, {%4,%5,%6,%7}, {%8,%9}, {%0,%1,%2,%3};\n"
        : "+f"(c[0]), "+f"(c[1]), "+f"(c[2]), "+f"(c[3])
        : "r"(a[0]), "r"(a[1]), "r"(a[2]), "r"(a[3]), "r"(b[0]), "r"(b[1]));
}

// ---------------------------------------------------------------------------
// Prepass: fp32 -> fp16, perm16 within 16-groups: out[4t..4t+3] = in[2t,2t+1,2t+8,2t+9]
// One thread = one 16-group -> two uint4 stores (packed order is linear).
// ---------------------------------------------------------------------------
__device__ __forceinline__ void prep16(const float* __restrict__ s, __half* __restrict__ d) {
    float v[16];
    *(float4*)(v)      = *(const float4*)(s);
    *(float4*)(v + 4)  = *(const float4*)(s + 4);
    *(float4*)(v + 8)  = *(const float4*)(s + 8);
    *(float4*)(v + 12) = *(const float4*)(s + 12);
    uint32_t o[8];
    #pragma unroll
    for (int t = 0; t < 4; t++) {
        o[2*t]     = packh(v[2*t],     v[2*t + 1]);
        o[2*t + 1] = packh(v[2*t + 8], v[2*t + 9]);
    }
    *(uint4*)(d)     = make_uint4(o[0], o[1], o[2], o[3]);
    *(uint4*)(d + 8) = make_uint4(o[4], o[5], o[6], o[7]);
}
__global__ void prep_x(const float* __restrict__ src) {
    int i = (blockIdx.x * blockDim.x + threadIdx.x) * 16;
    prep16(src + i, g_xh + i);
}
__global__ void prep_w(const float* w0, const float* w1, const float* w2, const float* w3) {
    const float* src = (blockIdx.y == 0) ? w0 : (blockIdx.y == 1) ? w1
                     : (blockIdx.y == 2) ? w2 : w3;
    long off = (long)blockIdx.y * C_ * C_;
    int i = (blockIdx.x * blockDim.x + threadIdx.x) * 16;
    prep16(src + i, g_Wh + off + i);
}

// ---------------------------------------------------------------------------
// GEMM-NT fp16 m16n8k16: C[m][n] = sum_k A[m][k]*B[n][k]. K=1024.
// 128x128 tile, BK=32, 256 thr (8 warps 4m x 2n), 2-stage cp.async.
// smem rows: 64B data + pad -> 96B pitch (conflict-free frag LDS.64).
// MODE 0: fp32 out. MODE 3: fused QKV epilogue (Q/K fp16 perm16, V fp16 plain).
// ---------------------------------------------------------------------------
#define GP 96                      // bytes per smem row
#define GTILE (128 * GP)           // 12288
#define GEMM_SMEM (4 * GTILE)      // A/B x 2 stages

template<int MODE>
__global__ void __launch_bounds__(256)
gemm_tc(const __half* __restrict__ A, const __half* __restrict__ Bm,
        float* __restrict__ Cm, __half* __restrict__ Cq,
        __half* __restrict__ Ck, __half* __restrict__ Cv)
{
    extern __shared__ char sm[];
    char* As = sm;                   // [2][128][GP]
    char* Bs = sm + 2 * GTILE;

    const int tid = threadIdx.x, lane = tid & 31, warp = tid >> 5;
    const int gid = lane >> 2, tig = lane & 3;
    const int wm = warp & 3, wn = warp >> 2;
    const int bm = blockIdx.y * 128, bn = blockIdx.x * 128;

    float acc[2][8][4];
    #pragma unroll
    for (int mt = 0; mt < 2; mt++)
        #pragma unroll
        for (int nt = 0; nt < 8; nt++)
            #pragma unroll
            for (int e = 0; e < 4; e++) acc[mt][nt][e] = 0.f;

    auto loadst = [&](int s, int kt) {
        #pragma unroll
        for (int t = 0; t < 2; t++) {
            int id = tid + t * 256;
            int row = id >> 2, seg = id & 3;
            cpa16(s2u(As + s * GTILE + row * GP + seg * 16),
                  A + (long)(bm + row) * C_ + kt + seg * 8);
            cpa16(s2u(Bs + s * GTILE + row * GP + seg * 16),
                  Bm + (long)(bn + row) * C_ + kt + seg * 8);
        }
    };

    loadst(0, 0); CPCOMMIT();

    #pragma unroll 2
    for (int t = 0; t < 32; t++) {
        CPWAIT0(); __syncthreads();
        if (t + 1 < 32) { loadst((t + 1) & 1, (t + 1) * 32); CPCOMMIT(); }
        const char* as = As + (t & 1) * GTILE;
        const char* bs = Bs + (t & 1) * GTILE;
        #pragma unroll
        for (int ck = 0; ck < 2; ck++) {
            int co = ck * 32 + tig * 8;
            uint32_t a[2][4];
            #pragma unroll
            for (int mt = 0; mt < 2; mt++) {
                int r = wm * 32 + mt * 16 + gid;
                uint2 lo = *(const uint2*)(as + r * GP + co);
                uint2 hi = *(const uint2*)(as + (r + 8) * GP + co);
                a[mt][0] = lo.x; a[mt][1] = hi.x; a[mt][2] = lo.y; a[mt][3] = hi.y;
            }
            #pragma unroll
            for (int nt = 0; nt < 8; nt++) {
                int r = wn * 64 + nt * 8 + gid;
                uint2 bv = *(const uint2*)(bs + r * GP + co);
                uint32_t b[2] = { bv.x, bv.y };
                mma_f16(acc[0][nt], a[0], b);
                mma_f16(acc[1][nt], a[1], b);
            }
        }
    }

    #pragma unroll
    for (int mt = 0; mt < 2; mt++) {
        #pragma unroll
        for (int nt = 0; nt < 8; nt++) {
            int r1 = bm + wm * 32 + mt * 16 + gid;
            int r2 = r1 + 8;
            int n0 = bn + wn * 64 + nt * 8 + 2 * tig;
            if (MODE == 0) {
                *(float2*)&Cm[(long)r1 * C_ + n0] = make_float2(acc[mt][nt][0], acc[mt][nt][1]);
                *(float2*)&Cm[(long)r2 * C_ + n0] = make_float2(acc[mt][nt][2], acc[mt][nt][3]);
            } else {
                int w  = n0 >> 10;          // 0=Q, 1=K, 2=V
                int nc = n0 & 1023;
                if (w == 2) {
                    *(uint32_t*)&Cv[(long)r1 * C_ + nc] = packh(acc[mt][nt][0], acc[mt][nt][1]);
                    *(uint32_t*)&Cv[(long)r2 * C_ + nc] = packh(acc[mt][nt][2], acc[mt][nt][3]);
                } else {
                    __half* dst = (w == 0) ? Cq : Ck;
                    int pp = (nc & ~15) | (4 * tig + 2 * ((nc >> 3) & 1));   // perm16 pair pos
                    *(uint32_t*)&dst[(long)r1 * C_ + pp] = packh(acc[mt][nt][0], acc[mt][nt][1]);
                    *(uint32_t*)&dst[(long)r2 * C_ + pp] = packh(acc[mt][nt][2], acc[mt][nt][3]);
                }
            }
        }
    }
}

// ---------------------------------------------------------------------------
// V transpose fp16: g_Vt[(b*16+h)*64+d][t0 + perm16(t)] = g_V[b*T+t][h*64+d]
// Block 256 thr; 32x32 tile.
// ---------------------------------------------------------------------------
__global__ void vtrans()
{
    __shared__ __half tile[32][36];
    const int t0 = blockIdx.x * 32, c0 = blockIdx.y * 32, b = blockIdx.z;
    const int tid = threadIdx.x;

    {
        int row = tid >> 3, seg = tid & 7;
        *(uint2*)&tile[row][seg * 4] =
            *(const uint2*)&g_V[(long)(b * T_ + t0 + row) * C_ + c0 + seg * 4];
    }
    __syncthreads();

    const int u = tid & 15, dc = tid >> 4;
    const int pos = 16 * (u >> 3) + 4 * (u & 3) + 2 * ((u >> 2) & 1);
    #pragma unroll
    for (int r = 0; r < 2; r++) {
        int d = dc + r * 16;
        __half2 val = __halves2half2(tile[2 * u][d], tile[2 * u + 1][d]);
        int cc = c0 + d, h = cc >> 6, dd = cc & 63;
        *(uint32_t*)&g_Vt[(long)(((b << 4) + h) * 64 + dd) * T_ + t0 + pos] =
            *(uint32_t*)&val;
    }
}

// ---------------------------------------------------------------------------
// Flash attention (causal), fp16 m16n8k16. BQ=128, 128 thr = 4 warps x 32 rows.
// Double-buffered KV, one barrier per tile, P C-frag -> A-frag by direct packs.
// smem: Q[128] + 2x(K[64]+V[64]) rows at 160B pitch = 60KB -> 2 CTAs/SM.
// ---------------------------------------------------------------------------
#define AP 160
#define AQ_BYTES (128 * AP)
#define AKV_BYTES (64 * AP)
#define ATTN_SMEM (AQ_BYTES + 4 * AKV_BYTES)

__global__ void __launch_bounds__(128, 2)
attn_tc()
{
    extern __shared__ char sm[];
    char* Qs  = sm;
    char* Kst = sm + AQ_BYTES;
    char* Vst = sm + AQ_BYTES + 2 * AKV_BYTES;

    const int qb = gridDim.x - 1 - blockIdx.x;    // big tiles first
    const int bh = blockIdx.y, bb = bh >> 4, h = bh & 15;
    const int tid = threadIdx.x, lane = tid & 31, warp = tid >> 5;
    const int gid = lane >> 2, tig = lane & 3;
    const int m0 = warp * 32;
    const int co0 = tig * 8;

    const long kbase0 = ((long)(bb * T_)) * C_ + h * 64;
    const long vbase0 = ((long)((bb * 16 + h) * 64)) * T_;

    auto load_kv = [&](int kb, int s) {
        char* Ks = Kst + s * AKV_BYTES;
        char* Vs = Vst + s * AKV_BYTES;
        const long kbase = kbase0 + (long)(kb * 64) * C_;
        const long vbase = vbase0 + kb * 64;
        #pragma unroll
        for (int j = 0; j < 4; j++) {
            int id = tid + j * 128;
            int row = id >> 3, seg = id & 7;
            cpa16(s2u(Ks + row * AP + seg * 16), g_K  + kbase + (long)row * C_ + seg * 8);
            cpa16(s2u(Vs + row * AP + seg * 16), g_Vt + vbase + (long)row * T_ + seg * 8);
        }
    };

    // Prologue: Q (128 rows) + KV tile 0.
    #pragma unroll
    for (int j = 0; j < 8; j++) {
        int id = tid + j * 128;
        int row = id >> 3, seg = id & 7;
        cpa16(s2u(Qs + row * AP + seg * 16),
              g_Q + kbase0 + (long)(qb * 128 + row) * C_ + seg * 8);
    }
    load_kv(0, 0);
    CPCOMMIT();

    float mr[2][2], lsum[2][2];
    #pragma unroll
    for (int mt = 0; mt < 2; mt++) {
        mr[mt][0] = -INFINITY; mr[mt][1] = -INFINITY;
        lsum[mt][0] = 0.f;     lsum[mt][1] = 0.f;
    }
    float oacc[2][8][4];
    #pragma unroll
    for (int mt = 0; mt < 2; mt++)
        #pragma unroll
        for (int nt = 0; nt < 8; nt++)
            #pragma unroll
            for (int e = 0; e < 4; e++) oacc[mt][nt][e] = 0.f;

    const int nkb = 2 * qb + 2;
    for (int kb = 0; kb < nkb; kb++) {
        const int s = kb & 1;
        char* Ks = Kst + s * AKV_BYTES;
        char* Vs = Vst + s * AKV_BYTES;

        CPWAIT0();
        __syncthreads();
        if (kb + 1 < nkb) { load_kv(kb + 1, s ^ 1); CPCOMMIT(); }

        if (kb == nkb - 1 && m0 < 64) continue;   // fully masked warp-tile

        // ---- S = Q @ K^T (4 k16 chunks over D=64) ----
        float sacc[2][8][4];
        #pragma unroll
        for (int mt = 0; mt < 2; mt++)
            #pragma unroll
            for (int nt = 0; nt < 8; nt++)
                #pragma unroll
                for (int e = 0; e < 4; e++) sacc[mt][nt][e] = 0.f;

        #pragma unroll
        for (int ck = 0; ck < 4; ck++) {
            int co = ck * 32 + co0;
            uint32_t a[2][4];
            #pragma unroll
            for (int mt = 0; mt < 2; mt++) {
                int r = m0 + mt * 16 + gid;
                uint2 lo = *(const uint2*)(Qs + r * AP + co);
                uint2 hi = *(const uint2*)(Qs + (r + 8) * AP + co);
                a[mt][0] = lo.x; a[mt][1] = hi.x; a[mt][2] = lo.y; a[mt][3] = hi.y;
            }
            #pragma unroll
            for (int nt = 0; nt < 8; nt++) {
                uint2 bv = *(const uint2*)(Ks + (nt * 8 + gid) * AP + co);
                uint32_t b[2] = { bv.x, bv.y };
                mma_f16(sacc[0][nt], a[0], b);
                mma_f16(sacc[1][nt], a[1], b);
            }
        }

        // ---- softmax (log2 domain) + pack P to fp16 A-frags ----
        const int dd = (kb - 2 * qb) * 64;
        const bool diag = (kb >= 2 * qb);
        uint32_t pfrag[2][4][4];   // [mt][ck][areg]
        #pragma unroll
        for (int mt = 0; mt < 2; mt++) {
            float mx0 = -INFINITY, mx1 = -INFINITY;
            #pragma unroll
            for (int nt = 0; nt < 8; nt++) {
                #pragma unroll
                for (int e = 0; e < 4; e++) {
                    float sv = sacc[mt][nt][e] * K2L;
                    if (diag) {
                        int rl = m0 + mt * 16 + gid + ((e >> 1) << 3);
                        int cl = nt * 8 + 2 * tig + (e & 1);
                        if (cl + dd > rl) sv = -INFINITY;
                    }
                    sacc[mt][nt][e] = sv;
                }
                mx0 = fmaxf(mx0, fmaxf(sacc[mt][nt][0], sacc[mt][nt][1]));
                mx1 = fmaxf(mx1, fmaxf(sacc[mt][nt][2], sacc[mt][nt][3]));
            }
            mx0 = fmaxf(mx0, __shfl_xor_sync(~0u, mx0, 1));
            mx0 = fmaxf(mx0, __shfl_xor_sync(~0u, mx0, 2));
            mx1 = fmaxf(mx1, __shfl_xor_sync(~0u, mx1, 1));
            mx1 = fmaxf(mx1, __shfl_xor_sync(~0u, mx1, 2));
            float mn0 = fmaxf(mr[mt][0], mx0), mn1 = fmaxf(mr[mt][1], mx1);
            float al0 = ex2f(mr[mt][0] - mn0), al1 = ex2f(mr[mt][1] - mn1);
            float rs0 = 0.f, rs1 = 0.f;
            #pragma unroll
            for (int nt = 0; nt < 8; nt++) {
                sacc[mt][nt][0] = ex2f(sacc[mt][nt][0] - mn0); rs0 += sacc[mt][nt][0];
                sacc[mt][nt][1] = ex2f(sacc[mt][nt][1] - mn0); rs0 += sacc[mt][nt][1];
                sacc[mt][nt][2] = ex2f(sacc[mt][nt][2] - mn1); rs1 += sacc[mt][nt][2];
                sacc[mt][nt][3] = ex2f(sacc[mt][nt][3] - mn1); rs1 += sacc[mt][nt][3];
            }
            rs0 += __shfl_xor_sync(~0u, rs0, 1);
            rs0 += __shfl_xor_sync(~0u, rs0, 2);
            rs1 += __shfl_xor_sync(~0u, rs1, 1);
            rs1 += __shfl_xor_sync(~0u, rs1, 2);
            lsum[mt][0] = lsum[mt][0] * al0 + rs0;
            lsum[mt][1] = lsum[mt][1] * al1 + rs1;
            mr[mt][0] = mn0;  mr[mt][1] = mn1;
            #pragma unroll
            for (int nt = 0; nt < 8; nt++) {
                oacc[mt][nt][0] *= al0; oacc[mt][nt][1] *= al0;
                oacc[mt][nt][2] *= al1; oacc[mt][nt][3] *= al1;
            }
            // C-frag pairs ARE the A-frag pairs for m16n8k16: direct packs.
            #pragma unroll
            for (int ck = 0; ck < 4; ck++) {
                pfrag[mt][ck][0] = packh(sacc[mt][2*ck][0],     sacc[mt][2*ck][1]);
                pfrag[mt][ck][1] = packh(sacc[mt][2*ck][2],     sacc[mt][2*ck][3]);
                pfrag[mt][ck][2] = packh(sacc[mt][2*ck + 1][0], sacc[mt][2*ck + 1][1]);
                pfrag[mt][ck][3] = packh(sacc[mt][2*ck + 1][2], sacc[mt][2*ck + 1][3]);
            }
        }

        // ---- O += P @ V (V B-frags shared across both m-strips) ----
        #pragma unroll
        for (int ck = 0; ck < 4; ck++) {
            int co = ck * 32 + co0;
            #pragma unroll
            for (int nt = 0; nt < 8; nt++) {
                uint2 bv = *(const uint2*)(Vs + (nt * 8 + gid) * AP + co);
                uint32_t b[2] = { bv.x, bv.y };
                mma_f16(oacc[0][nt], pfrag[0][ck], b);
                mma_f16(oacc[1][nt], pfrag[1][ck], b);
            }
        }
    }

    // ---- finalize: AO fp16 perm16 for O-projection GEMM ----
    #pragma unroll
    for (int mt = 0; mt < 2; mt++) {
        float inv0 = 1.f / lsum[mt][0], inv1 = 1.f / lsum[mt][1];
        long base = ((long)(bb * T_ + qb * 128 + m0 + mt * 16 + gid)) * C_ + h * 64;
        #pragma unroll
        for (int nt = 0; nt < 8; nt++) {
            int pp = (nt >> 1) * 16 + 4 * tig + 2 * (nt & 1);
            *(uint32_t*)&g_AO[base + pp] =
                packh(oacc[mt][nt][0] * inv0, oacc[mt][nt][1] * inv0);
            *(uint32_t*)&g_AO[base + 8L * C_ + pp] =
                packh(oacc[mt][nt][2] * inv1, oacc[mt][nt][3] * inv1);
        }
    }
}

// ---------------------------------------------------------------------------
extern "C" void kernel_launch(void* const* d_in, const int* in_sizes, int n_in,
                              void* d_out, int out_size)
{
    const float* x  = (const float*)d_in[0];
    const float* Wq = (const float*)d_in[1];
    const float* Wk = (const float*)d_in[2];
    const float* Wv = (const float*)d_in[3];
    const float* Wo = (const float*)d_in[4];
    float* out = (float*)d_out;

    __half *xh, *Wh, *Q, *K, *V, *AO;
    cudaGetSymbolAddress((void**)&xh, g_xh);
    cudaGetSymbolAddress((void**)&Wh, g_Wh);
    cudaGetSymbolAddress((void**)&Q,  g_Q);
    cudaGetSymbolAddress((void**)&K,  g_K);
    cudaGetSymbolAddress((void**)&V,  g_V);
    cudaGetSymbolAddress((void**)&AO, g_AO);

    cudaFuncSetAttribute(gemm_tc<0>, cudaFuncAttributeMaxDynamicSharedMemorySize, GEMM_SMEM);
    cudaFuncSetAttribute(gemm_tc<3>, cudaFuncAttributeMaxDynamicSharedMemorySize, GEMM_SMEM);
    cudaFuncSetAttribute(attn_tc,    cudaFuncAttributeMaxDynamicSharedMemorySize, ATTN_SMEM);

    prep_x<<<1024, 256>>>(x);
    prep_w<<<dim3(256, 4), 256>>>(Wq, Wk, Wv, Wo);

    // Fused QKV projection: B = [Wq; Wk; Wv] rows 0..3071 of g_Wh.
    gemm_tc<3><<<dim3(24, 32), 256, GEMM_SMEM>>>(xh, Wh, nullptr, Q, K, V);

    vtrans<<<dim3(T_ / 32, C_ / 32, B_), 256>>>();

    attn_tc<<<dim3(T_ / 128, B_ * H_), 128, ATTN_SMEM>>>();

    gemm_tc<0><<<dim3(8, 32), 256, GEMM_SMEM>>>(AO, Wh + 3L * C_ * C_, out,
                                                nullptr, nullptr, nullptr);
}

// round 16
// speedup vs baseline: 2.3374x; 1.0150x over previous
#include <cuda_runtime.h>
#include <cuda_fp16.h>
#include <math.h>
#include <stdint.h>

#define B_ 2
#define T_ 2048
#define C_ 1024
#define H_ 16
#define D_ 64
#define M_ 4096
#define K2L 0.18033688f   // 0.125 * log2(e)

// Scratch (allocation-free), all fp16
__device__ __half g_xh[M_*C_];
__device__ __half g_Wh[4*C_*C_];
__device__ __half g_Q [M_*C_];
__device__ __half g_K [M_*C_];
__device__ __half g_V [M_*C_];
__device__ __half g_Vt[B_*H_*D_*T_];
__device__ __half g_AO[M_*C_];

// ---------------------------------------------------------------------------
__device__ __forceinline__ uint32_t s2u(const void* p) {
    return (uint32_t)__cvta_generic_to_shared(p);
}
__device__ __forceinline__ void cpa16(uint32_t d, const void* s) {
    asm volatile("cp.async.cg.shared.global [%0], [%1], 16;\n" :: "r"(d), "l"(s));
}
#define CPCOMMIT() asm volatile("cp.async.commit_group;\n")
#define CPWAIT0()  asm volatile("cp.async.wait_group 0;\n")
__device__ __forceinline__ float ex2f(float x) {
    float y; asm("ex2.approx.ftz.f32 %0, %1;" : "=f"(y) : "f"(x)); return y;
}
__device__ __forceinline__ uint32_t packh(float lo, float hi) {
    __half2 h = __floats2half2_rn(lo, hi);
    return *(uint32_t*)&h;
}
__device__ __forceinline__ uint32_t ex2h2(uint32_t x) {
    uint32_t r; asm("ex2.approx.f16x2 %0, %1;" : "=r"(r) : "r"(x)); return r;
}
// fp16 m16n8k16, fp32 accumulate
__device__ __forceinline__ void mma_f16(float* c, const uint32_t* a, const uint32_t* b) {
    asm volatile(
        "mma.sync.aligned.m16n8k16.row.col.f32.f16.f16.f32 "
        "{%0,%1,%2,%3}, {%4,%5,%6,%7}, {%8,%9}, {%0,%1,%2,%3};\n"
        : "+f"(c[0]), "+f"(c[1]), "+f"(c[2]), "+f"(c[3])
        : "r"(a[0]), "r"(a[1]), "r"(a[2]), "r"(a[3]), "r"(b[0]), "r"(b[1]));
}

// ---------------------------------------------------------------------------
// Prepass: fp32 -> fp16, perm16 within 16-groups: out[4t..4t+3] = in[2t,2t+1,2t+8,2t+9]
// ---------------------------------------------------------------------------
__device__ __forceinline__ void prep16(const float* __restrict__ s, __half* __restrict__ d) {
    float v[16];
    *(float4*)(v)      = *(const float4*)(s);
    *(float4*)(v + 4)  = *(const float4*)(s + 4);
    *(float4*)(v + 8)  = *(const float4*)(s + 8);
    *(float4*)(v + 12) = *(const float4*)(s + 12);
    uint32_t o[8];
    #pragma unroll
    for (int t = 0; t < 4; t++) {
        o[2*t]     = packh(v[2*t],     v[2*t + 1]);
        o[2*t + 1] = packh(v[2*t + 8], v[2*t + 9]);
    }
    *(uint4*)(d)     = make_uint4(o[0], o[1], o[2], o[3]);
    *(uint4*)(d + 8) = make_uint4(o[4], o[5], o[6], o[7]);
}
__global__ void prep_x(const float* __restrict__ src) {
    int i = (blockIdx.x * blockDim.x + threadIdx.x) * 16;
    prep16(src + i, g_xh + i);
}
__global__ void prep_w(const float* w0, const float* w1, const float* w2, const float* w3) {
    const float* src = (blockIdx.y == 0) ? w0 : (blockIdx.y == 1) ? w1
                     : (blockIdx.y == 2) ? w2 : w3;
    long off = (long)blockIdx.y * C_ * C_;
    int i = (blockIdx.x * blockDim.x + threadIdx.x) * 16;
    prep16(src + i, g_Wh + off + i);
}

// ---------------------------------------------------------------------------
// GEMM-NT fp16 m16n8k16 (validated R14). MODE 0: fp32 out. MODE 3: fused QKV.
// ---------------------------------------------------------------------------
#define GP 96
#define GTILE (128 * GP)
#define GEMM_SMEM (4 * GTILE)

template<int MODE>
__global__ void __launch_bounds__(256)
gemm_tc(const __half* __restrict__ A, const __half* __restrict__ Bm,
        float* __restrict__ Cm, __half* __restrict__ Cq,
        __half* __restrict__ Ck, __half* __restrict__ Cv)
{
    extern __shared__ char sm[];
    char* As = sm;
    char* Bs = sm + 2 * GTILE;

    const int tid = threadIdx.x, lane = tid & 31, warp = tid >> 5;
    const int gid = lane >> 2, tig = lane & 3;
    const int wm = warp & 3, wn = warp >> 2;
    const int bm = blockIdx.y * 128, bn = blockIdx.x * 128;

    float acc[2][8][4];
    #pragma unroll
    for (int mt = 0; mt < 2; mt++)
        #pragma unroll
        for (int nt = 0; nt < 8; nt++)
            #pragma unroll
            for (int e = 0; e < 4; e++) acc[mt][nt][e] = 0.f;

    auto loadst = [&](int s, int kt) {
        #pragma unroll
        for (int t = 0; t < 2; t++) {
            int id = tid + t * 256;
            int row = id >> 2, seg = id & 3;
            cpa16(s2u(As + s * GTILE + row * GP + seg * 16),
                  A + (long)(bm + row) * C_ + kt + seg * 8);
            cpa16(s2u(Bs + s * GTILE + row * GP + seg * 16),
                  Bm + (long)(bn + row) * C_ + kt + seg * 8);
        }
    };

    loadst(0, 0); CPCOMMIT();

    #pragma unroll 2
    for (int t = 0; t < 32; t++) {
        CPWAIT0(); __syncthreads();
        if (t + 1 < 32) { loadst((t + 1) & 1, (t + 1) * 32); CPCOMMIT(); }
        const char* as = As + (t & 1) * GTILE;
        const char* bs = Bs + (t & 1) * GTILE;
        #pragma unroll
        for (int ck = 0; ck < 2; ck++) {
            int co = ck * 32 + tig * 8;
            uint32_t a[2][4];
            #pragma unroll
            for (int mt = 0; mt < 2; mt++) {
                int r = wm * 32 + mt * 16 + gid;
                uint2 lo = *(const uint2*)(as + r * GP + co);
                uint2 hi = *(const uint2*)(as + (r + 8) * GP + co);
                a[mt][0] = lo.x; a[mt][1] = hi.x; a[mt][2] = lo.y; a[mt][3] = hi.y;
            }
            #pragma unroll
            for (int nt = 0; nt < 8; nt++) {
                int r = wn * 64 + nt * 8 + gid;
                uint2 bv = *(const uint2*)(bs + r * GP + co);
                uint32_t b[2] = { bv.x, bv.y };
                mma_f16(acc[0][nt], a[0], b);
                mma_f16(acc[1][nt], a[1], b);
            }
        }
    }

    #pragma unroll
    for (int mt = 0; mt < 2; mt++) {
        #pragma unroll
        for (int nt = 0; nt < 8; nt++) {
            int r1 = bm + wm * 32 + mt * 16 + gid;
            int r2 = r1 + 8;
            int n0 = bn + wn * 64 + nt * 8 + 2 * tig;
            if (MODE == 0) {
                *(float2*)&Cm[(long)r1 * C_ + n0] = make_float2(acc[mt][nt][0], acc[mt][nt][1]);
                *(float2*)&Cm[(long)r2 * C_ + n0] = make_float2(acc[mt][nt][2], acc[mt][nt][3]);
            } else {
                int w  = n0 >> 10;          // 0=Q, 1=K, 2=V
                int nc = n0 & 1023;
                if (w == 2) {
                    *(uint32_t*)&Cv[(long)r1 * C_ + nc] = packh(acc[mt][nt][0], acc[mt][nt][1]);
                    *(uint32_t*)&Cv[(long)r2 * C_ + nc] = packh(acc[mt][nt][2], acc[mt][nt][3]);
                } else {
                    __half* dst = (w == 0) ? Cq : Ck;
                    int pp = (nc & ~15) | (4 * tig + 2 * ((nc >> 3) & 1));   // perm16 pair pos
                    *(uint32_t*)&dst[(long)r1 * C_ + pp] = packh(acc[mt][nt][0], acc[mt][nt][1]);
                    *(uint32_t*)&dst[(long)r2 * C_ + pp] = packh(acc[mt][nt][2], acc[mt][nt][3]);
                }
            }
        }
    }
}

// ---------------------------------------------------------------------------
// V transpose fp16 (validated R14).
// ---------------------------------------------------------------------------
__global__ void vtrans()
{
    __shared__ __half tile[32][36];
    const int t0 = blockIdx.x * 32, c0 = blockIdx.y * 32, b = blockIdx.z;
    const int tid = threadIdx.x;

    {
        int row = tid >> 3, seg = tid & 7;
        *(uint2*)&tile[row][seg * 4] =
            *(const uint2*)&g_V[(long)(b * T_ + t0 + row) * C_ + c0 + seg * 4];
    }
    __syncthreads();

    const int u = tid & 15, dc = tid >> 4;
    const int pos = 16 * (u >> 3) + 4 * (u & 3) + 2 * ((u >> 2) & 1);
    #pragma unroll
    for (int r = 0; r < 2; r++) {
        int d = dc + r * 16;
        __half2 val = __halves2half2(tile[2 * u][d], tile[2 * u + 1][d]);
        int cc = c0 + d, h = cc >> 6, dd = cc & 63;
        *(uint32_t*)&g_Vt[(long)(((b << 4) + h) * 64 + dd) * T_ + t0 + pos] =
            *(uint32_t*)&val;
    }
}

// ---------------------------------------------------------------------------
// Flash attention (causal), fp16 m16n8k16. BQ=128, 128 thr = 4 warps x 32 rows.
// ex2.approx.f16x2 softmax (output IS the P A-frag) and row-sums l via
// P @ ones (9th n-group; Vs rows 64-71 hold 1.0; racc rescaled like O).
// smem: Q[128] + 2xK[64] + 2xV[72] rows @160B = 64000B -> 2 CTAs/SM.
// ---------------------------------------------------------------------------
#define AP 160
#define AQ_BYTES  (128 * AP)
#define K64_BYTES (64 * AP)
#define V72_BYTES (72 * AP)
#define ATTN_SMEM (AQ_BYTES + 2 * K64_BYTES + 2 * V72_BYTES)

__global__ void __launch_bounds__(128, 2)
attn_tc()
{
    extern __shared__ char sm[];
    char* Qs  = sm;
    char* Kst = sm + AQ_BYTES;
    char* Vst = sm + AQ_BYTES + 2 * K64_BYTES;

    const int qb = gridDim.x - 1 - blockIdx.x;    // big tiles first
    const int bh = blockIdx.y, bb = bh >> 4, h = bh & 15;
    const int tid = threadIdx.x, lane = tid & 31, warp = tid >> 5;
    const int gid = lane >> 2, tig = lane & 3;
    const int m0 = warp * 32;
    const int co0 = tig * 8;

    const long kbase0 = ((long)(bb * T_)) * C_ + h * 64;
    const long vbase0 = ((long)((bb * 16 + h) * 64)) * T_;

    auto load_kv = [&](int kb, int s) {
        char* Ks = Kst + s * K64_BYTES;
        char* Vs = Vst + s * V72_BYTES;
        const long kbase = kbase0 + (long)(kb * 64) * C_;
        const long vbase = vbase0 + kb * 64;
        #pragma unroll
        for (int j = 0; j < 4; j++) {
            int id = tid + j * 128;
            int row = id >> 3, seg = id & 7;
            cpa16(s2u(Ks + row * AP + seg * 16), g_K  + kbase + (long)row * C_ + seg * 8);
            cpa16(s2u(Vs + row * AP + seg * 16), g_Vt + vbase + (long)row * T_ + seg * 8);
        }
    };

    // Prologue: Q (128 rows) + KV tile 0; ones rows (64-71) of both V stages.
    #pragma unroll
    for (int j = 0; j < 8; j++) {
        int id = tid + j * 128;
        int row = id >> 3, seg = id & 7;
        cpa16(s2u(Qs + row * AP + seg * 16),
              g_Q + kbase0 + (long)(qb * 128 + row) * C_ + seg * 8);
    }
    load_kv(0, 0);
    CPCOMMIT();
    {
        int s = tid >> 6, r = (tid >> 3) & 7, seg = tid & 7;
        uint4 one4 = make_uint4(0x3C003C00u, 0x3C003C00u, 0x3C003C00u, 0x3C003C00u);
        *(uint4*)(Vst + s * V72_BYTES + (64 + r) * AP + seg * 16) = one4;
    }

    float mr[2][2];
    #pragma unroll
    for (int mt = 0; mt < 2; mt++) { mr[mt][0] = -INFINITY; mr[mt][1] = -INFINITY; }
    float oacc[2][8][4], racc[2][4];
    #pragma unroll
    for (int mt = 0; mt < 2; mt++) {
        #pragma unroll
        for (int nt = 0; nt < 8; nt++)
            #pragma unroll
            for (int e = 0; e < 4; e++) oacc[mt][nt][e] = 0.f;
        #pragma unroll
        for (int e = 0; e < 4; e++) racc[mt][e] = 0.f;
    }

    const int nkb = 2 * qb + 2;
    for (int kb = 0; kb < nkb; kb++) {
        const int s = kb & 1;
        char* Ks = Kst + s * K64_BYTES;
        char* Vs = Vst + s * V72_BYTES;

        CPWAIT0();
        __syncthreads();
        if (kb + 1 < nkb) { load_kv(kb + 1, s ^ 1); CPCOMMIT(); }

        if (kb == nkb - 1 && m0 < 64) continue;   // fully masked warp-tile

        // ---- S = Q @ K^T ----
        float sacc[2][8][4];
        #pragma unroll
        for (int mt = 0; mt < 2; mt++)
            #pragma unroll
            for (int nt = 0; nt < 8; nt++)
                #pragma unroll
                for (int e = 0; e < 4; e++) sacc[mt][nt][e] = 0.f;

        #pragma unroll
        for (int ck = 0; ck < 4; ck++) {
            int co = ck * 32 + co0;
            uint32_t a[2][4];
            #pragma unroll
            for (int mt = 0; mt < 2; mt++) {
                int r = m0 + mt * 16 + gid;
                uint2 lo = *(const uint2*)(Qs + r * AP + co);
                uint2 hi = *(const uint2*)(Qs + (r + 8) * AP + co);
                a[mt][0] = lo.x; a[mt][1] = hi.x; a[mt][2] = lo.y; a[mt][3] = hi.y;
            }
            #pragma unroll
            for (int nt = 0; nt < 8; nt++) {
                uint2 bv = *(const uint2*)(Ks + (nt * 8 + gid) * AP + co);
                uint32_t b[2] = { bv.x, bv.y };
                mma_f16(sacc[0][nt], a[0], b);
                mma_f16(sacc[1][nt], a[1], b);
            }
        }

        // ---- softmax: scale+mask, max, then f16x2 exp straight into A-frags ----
        const int dd = (kb - 2 * qb) * 64;
        const bool diag = (kb >= 2 * qb);
        uint32_t pfrag[2][4][4];
        #pragma unroll
        for (int mt = 0; mt < 2; mt++) {
            float mx0 = -INFINITY, mx1 = -INFINITY;
            #pragma unroll
            for (int nt = 0; nt < 8; nt++) {
                #pragma unroll
                for (int e = 0; e < 4; e++) {
                    float sv = sacc[mt][nt][e] * K2L;
                    if (diag) {
                        int rl = m0 + mt * 16 + gid + ((e >> 1) << 3);
                        int cl = nt * 8 + 2 * tig + (e & 1);
                        if (cl + dd > rl) sv = -INFINITY;
                    }
                    sacc[mt][nt][e] = sv;
                }
                mx0 = fmaxf(mx0, fmaxf(sacc[mt][nt][0], sacc[mt][nt][1]));
                mx1 = fmaxf(mx1, fmaxf(sacc[mt][nt][2], sacc[mt][nt][3]));
            }
            mx0 = fmaxf(mx0, __shfl_xor_sync(~0u, mx0, 1));
            mx0 = fmaxf(mx0, __shfl_xor_sync(~0u, mx0, 2));
            mx1 = fmaxf(mx1, __shfl_xor_sync(~0u, mx1, 1));
            mx1 = fmaxf(mx1, __shfl_xor_sync(~0u, mx1, 2));
            float mn0 = fmaxf(mr[mt][0], mx0), mn1 = fmaxf(mr[mt][1], mx1);
            float al0 = ex2f(mr[mt][0] - mn0), al1 = ex2f(mr[mt][1] - mn1);
            mr[mt][0] = mn0;  mr[mt][1] = mn1;
            #pragma unroll
            for (int nt = 0; nt < 8; nt++) {
                uint32_t lo = packh(sacc[mt][nt][0] - mn0, sacc[mt][nt][1] - mn0);
                uint32_t hi = packh(sacc[mt][nt][2] - mn1, sacc[mt][nt][3] - mn1);
                pfrag[mt][nt >> 1][(nt & 1) * 2 + 0] = ex2h2(lo);
                pfrag[mt][nt >> 1][(nt & 1) * 2 + 1] = ex2h2(hi);
            }
            #pragma unroll
            for (int nt = 0; nt < 8; nt++) {
                oacc[mt][nt][0] *= al0; oacc[mt][nt][1] *= al0;
                oacc[mt][nt][2] *= al1; oacc[mt][nt][3] *= al1;
            }
            racc[mt][0] *= al0; racc[mt][1] *= al0;
            racc[mt][2] *= al1; racc[mt][3] *= al1;
        }

        // ---- O += P @ V; l += P @ ones (9th n-group, Vs rows 64-71) ----
        #pragma unroll
        for (int ck = 0; ck < 4; ck++) {
            int co = ck * 32 + co0;
            #pragma unroll
            for (int nt = 0; nt < 8; nt++) {
                uint2 bv = *(const uint2*)(Vs + (nt * 8 + gid) * AP + co);
                uint32_t b[2] = { bv.x, bv.y };
                mma_f16(oacc[0][nt], pfrag[0][ck], b);
                mma_f16(oacc[1][nt], pfrag[1][ck], b);
            }
            uint2 bo = *(const uint2*)(Vs + (64 + gid) * AP + co);
            uint32_t b1[2] = { bo.x, bo.y };
            mma_f16(racc[0], pfrag[0][ck], b1);
            mma_f16(racc[1], pfrag[1][ck], b1);
        }
    }

    // ---- finalize: l from racc (all cols equal); AO fp16 perm16 ----
    #pragma unroll
    for (int mt = 0; mt < 2; mt++) {
        float inv0 = 1.f / racc[mt][0], inv1 = 1.f / racc[mt][2];
        long base = ((long)(bb * T_ + qb * 128 + m0 + mt * 16 + gid)) * C_ + h * 64;
        #pragma unroll
        for (int nt = 0; nt < 8; nt++) {
            int pp = (nt >> 1) * 16 + 4 * tig + 2 * (nt & 1);
            *(uint32_t*)&g_AO[base + pp] =
                packh(oacc[mt][nt][0] * inv0, oacc[mt][nt][1] * inv0);
            *(uint32_t*)&g_AO[base + 8L * C_ + pp] =
                packh(oacc[mt][nt][2] * inv1, oacc[mt][nt][3] * inv1);
        }
    }
}

// ---------------------------------------------------------------------------
extern "C" void kernel_launch(void* const* d_in, const int* in_sizes, int n_in,
                              void* d_out, int out_size)
{
    const float* x  = (const float*)d_in[0];
    const float* Wq = (const float*)d_in[1];
    const float* Wk = (const float*)d_in[2];
    const float* Wv = (const float*)d_in[3];
    const float* Wo = (const float*)d_in[4];
    float* out = (float*)d_out;

    __half *xh, *Wh, *Q, *K, *V, *AO;
    cudaGetSymbolAddress((void**)&xh, g_xh);
    cudaGetSymbolAddress((void**)&Wh, g_Wh);
    cudaGetSymbolAddress((void**)&Q,  g_Q);
    cudaGetSymbolAddress((void**)&K,  g_K);
    cudaGetSymbolAddress((void**)&V,  g_V);
    cudaGetSymbolAddress((void**)&AO, g_AO);

    cudaFuncSetAttribute(gemm_tc<0>, cudaFuncAttributeMaxDynamicSharedMemorySize, GEMM_SMEM);
    cudaFuncSetAttribute(gemm_tc<3>, cudaFuncAttributeMaxDynamicSharedMemorySize, GEMM_SMEM);
    cudaFuncSetAttribute(attn_tc,    cudaFuncAttributeMaxDynamicSharedMemorySize, ATTN_SMEM);

    prep_x<<<1024, 256>>>(x);
    prep_w<<<dim3(256, 4), 256>>>(Wq, Wk, Wv, Wo);

    // Fused QKV projection: B = [Wq; Wk; Wv] rows 0..3071 of g_Wh.
    gemm_tc<3><<<dim3(24, 32), 256, GEMM_SMEM>>>(xh, Wh, nullptr, Q, K, V);

    vtrans<<<dim3(T_ / 32, C_ / 32, B_), 256>>>();

    attn_tc<<<dim3(T_ / 128, B_ * H_), 128, ATTN_SMEM>>>();

    gemm_tc<0><<<dim3(8, 32), 256, GEMM_SMEM>>>(AO, Wh + 3L * C_ * C_, out,
                                                nullptr, nullptr, nullptr);
}